// round 3
// baseline (speedup 1.0000x reference)
#include <cuda_runtime.h>

#define NN 2048
#define BB 16
#define DD 8
#define OTILE 256          // 64 threads.x * 4 floats
#define ECHUNK 56
#define ESPLIT 37          // 37*56 = 2072 >= 2048 ; 8*37 = 296 blocks = 2/SM exactly
#define APAD 132           // DD*BB (=128) padded to kill smem bank conflicts, 16B-aligned

// scratch (no allocs allowed)
__device__ float g_partial[ESPLIT * BB * NN];    // [split][b][o] (4.6 MB)

__global__ __launch_bounds__(256, 2)
void delta_syn_main(const float* __restrict__ W,
                    const float* __restrict__ Wlong,
                    const float* __restrict__ dm,
                    const float* __restrict__ frac,
                    const float* __restrict__ signs_pre,
                    const float* __restrict__ Xd,
                    const float* __restrict__ Wshort) {
    __shared__ float A_sm[ECHUNK * APAD];   // ~28.9 KB
    __shared__ float s_sign[ECHUNK];

    const int tx    = threadIdx.x;             // 0..63
    const int ty    = threadIdx.y;             // 0..3  -> b group of 4
    const int tid   = ty * 64 + tx;
    const int o     = blockIdx.x * OTILE + tx * 4;
    const int split = blockIdx.y;
    const int e0    = split * ECHUNK;
    const int e1    = min(NN, e0 + ECHUNK);
    const int ecnt  = e1 - e0;

    // ---- fused prep: signs + A[ee][d*16+b] = Xd*(Wshort+1) into smem ----
    for (int i = tid; i < ecnt; i += 256) {
        const float sp = signs_pre[e0 + i];
        s_sign[i] = (sp > 0.0f) ? 1.0f : ((sp < 0.0f) ? -1.0f : 0.0f);
    }
    for (int i = tid; i < ecnt * 128; i += 256) {
        const int ee = i >> 7;
        const int db = i & 127;                 // d*16 + b
        const int g  = (db << 11) + e0 + ee;    // d*(BB*NN) + b*NN + e  (db*2048)
        A_sm[ee * APAD + db] = Xd[g] * (Wshort[g] + 1.0f);
    }
    __syncthreads();

    float acc[4][4];
#pragma unroll
    for (int bi = 0; bi < 4; bi++)
#pragma unroll
        for (int oi = 0; oi < 4; oi++) acc[bi][oi] = 0.0f;

#pragma unroll 1
    for (int ee = 0; ee < ecnt; ee++) {
        const int e    = e0 + ee;
        const int base = e * NN + o;

        // ---- issue all global loads up front (MLP) ----
        const float4 w4 = *reinterpret_cast<const float4*>(W + base);
        const float4 f4 = *reinterpret_cast<const float4*>(frac + base);

        float4 dm4[DD];
#pragma unroll
        for (int d = 0; d < DD; d++)
            dm4[d] = *reinterpret_cast<const float4*>(dm + d * (NN * NN) + base);

        float4 wl4[4];
#pragma unroll
        for (int bi = 0; bi < 4; bi++) {
            const int b = ty * 4 + bi;
            wl4[bi] = __ldcs(reinterpret_cast<const float4*>(Wlong + b * (NN * NN) + base));
        }

        // ---- P/Q from W, frac, sign ----
        const float s = s_sign[ee];
        float wv[4] = {w4.x, w4.y, w4.z, w4.w};
        float fv[4] = {f4.x, f4.y, f4.z, f4.w};
        float P[4], Q[4];
#pragma unroll
        for (int oi = 0; oi < 4; oi++) {
            const bool m = wv[oi] > 0.0f;
            P[oi] = m ? s * wv[oi] * (1.0f - fv[oi]) : 0.0f;
            Q[oi] = m ? s * fv[oi] : 0.0f;
        }

        // ---- S[bi][oi] = sum_d A[d][b] * dm[d][o] ----
        float S[4][4];
#pragma unroll
        for (int bi = 0; bi < 4; bi++)
#pragma unroll
            for (int oi = 0; oi < 4; oi++) S[bi][oi] = 0.0f;

#pragma unroll
        for (int d = 0; d < DD; d++) {
            const float4 a4 = *reinterpret_cast<const float4*>(
                A_sm + ee * APAD + d * BB + ty * 4);
            const float av[4] = {a4.x, a4.y, a4.z, a4.w};
            const float dv[4] = {dm4[d].x, dm4[d].y, dm4[d].z, dm4[d].w};
#pragma unroll
            for (int bi = 0; bi < 4; bi++)
#pragma unroll
                for (int oi = 0; oi < 4; oi++)
                    S[bi][oi] = fmaf(av[bi], dv[oi], S[bi][oi]);
        }

        // ---- acc += (P + Q*Wlong) * S ----
#pragma unroll
        for (int bi = 0; bi < 4; bi++) {
            const float wlv[4] = {wl4[bi].x, wl4[bi].y, wl4[bi].z, wl4[bi].w};
#pragma unroll
            for (int oi = 0; oi < 4; oi++) {
                const float t = fmaf(Q[oi], wlv[oi], P[oi]);
                acc[bi][oi] = fmaf(t, S[bi][oi], acc[bi][oi]);
            }
        }
    }

    // deterministic split partials
#pragma unroll
    for (int bi = 0; bi < 4; bi++) {
        const int b = ty * 4 + bi;
        float4 v = make_float4(acc[bi][0], acc[bi][1], acc[bi][2], acc[bi][3]);
        *reinterpret_cast<float4*>(g_partial + (split * BB + b) * NN + o) = v;
    }
}

__global__ void reduce_partials(float* __restrict__ out) {
    const int i = blockIdx.x * blockDim.x + threadIdx.x;   // over BB*NN/4 float4s
    if (i >= BB * NN / 4) return;
    const float4* p = reinterpret_cast<const float4*>(g_partial);
    float sx = 0.f, sy = 0.f, sz = 0.f, sw = 0.f;
#pragma unroll
    for (int sp = 0; sp < ESPLIT; sp++) {
        const float4 v = p[sp * (BB * NN / 4) + i];
        sx += v.x; sy += v.y; sz += v.z; sw += v.w;
    }
    reinterpret_cast<float4*>(out)[i] = make_float4(sx, sy, sz, sw);
}

extern "C" void kernel_launch(void* const* d_in, const int* in_sizes, int n_in,
                              void* d_out, int out_size) {
    const float* W         = (const float*)d_in[0];  // (N,N)
    const float* Wlong     = (const float*)d_in[1];  // (B,N,N)
    const float* Wshort    = (const float*)d_in[2];  // (D,B,N)
    const float* Xd        = (const float*)d_in[3];  // (D,B,N)
    const float* delaymap  = (const float*)d_in[4];  // (D,N,N)
    const float* STDP_frac = (const float*)d_in[5];  // (N,N)
    const float* signs_pre = (const float*)d_in[6];  // (N,)
    float* out = (float*)d_out;                      // (B,N)

    dim3 grid(NN / OTILE, ESPLIT);   // (8, 37) = 296 blocks
    dim3 block(64, 4);
    delta_syn_main<<<grid, block>>>(W, Wlong, delaymap, STDP_frac, signs_pre,
                                    Xd, Wshort);

    reduce_partials<<<(BB * NN / 4 + 255) / 256, 256>>>(out);
}

// round 4
// speedup vs baseline: 1.1273x; 1.1273x over previous
#include <cuda_runtime.h>

#define NN 2048
#define BB 16
#define DD 8
#define OTILE 256          // 64 threads.x * 4 floats
#define ECHUNK 56
#define ESPLIT 37          // 37*56 = 2072 >= 2048 ; 8*37 = 296 blocks = 2/SM exactly

// scratch (no allocs allowed)
__device__ float g_A[NN * DD * BB];              // [e][d*16+b]  (1 MB)
__device__ float g_partial[ESPLIT * BB * NN];    // [split][b][o] (4.6 MB)

// A[e][db] = Xd[db][e] * (Wshort[db][e] + 1)  via smem-tiled transpose.
// Source rows db (128), cols e (2048). 32x32 tiles, coalesced read AND write.
__global__ __launch_bounds__(256)
void prep_A_t(const float* __restrict__ Xd, const float* __restrict__ Wshort) {
    __shared__ float tile[32][33];
    const int tx = threadIdx.x;            // 0..31
    const int ty = threadIdx.y;            // 0..7
    const int e_base  = blockIdx.x * 32;   // 64 tiles
    const int db_base = blockIdx.y * 32;   // 4 tiles

#pragma unroll
    for (int j = 0; j < 4; j++) {
        const int db = db_base + ty + j * 8;
        const int e  = e_base + tx;
        const int g  = db * NN + e;        // coalesced: consecutive tx -> consecutive e
        tile[ty + j * 8][tx] = Xd[g] * (Wshort[g] + 1.0f);
    }
    __syncthreads();
#pragma unroll
    for (int j = 0; j < 4; j++) {
        const int e  = e_base + ty + j * 8;
        const int db = db_base + tx;
        // coalesced: consecutive tx -> consecutive db (row of 128 floats)
        g_A[e * (DD * BB) + db] = tile[tx][ty + j * 8];
    }
}

__global__ __launch_bounds__(256, 2)
void delta_syn_main(const float* __restrict__ W,
                    const float* __restrict__ Wlong,
                    const float* __restrict__ dm,
                    const float* __restrict__ frac,
                    const float* __restrict__ signs_pre) {
    __shared__ float A_sm[ECHUNK * DD * BB];   // 28 KB

    const int tx    = threadIdx.x;             // 0..63
    const int ty    = threadIdx.y;             // 0..3  -> b group of 4
    const int tid   = ty * 64 + tx;
    const int o     = blockIdx.x * OTILE + tx * 4;
    const int split = blockIdx.y;
    const int e0    = split * ECHUNK;
    const int e1    = min(NN, e0 + ECHUNK);
    const int ecnt  = e1 - e0;

    // stage A[e0:e1][d][b] into smem (contiguous float4 copy)
    {
        const float4* src = reinterpret_cast<const float4*>(g_A + e0 * (DD * BB));
        float4* dst = reinterpret_cast<float4*>(A_sm);
        const int nvec = ecnt * (DD * BB) / 4;
        for (int i = tid; i < nvec; i += 256) dst[i] = src[i];
    }
    __syncthreads();

    float acc[4][4];
#pragma unroll
    for (int bi = 0; bi < 4; bi++)
#pragma unroll
        for (int oi = 0; oi < 4; oi++) acc[bi][oi] = 0.0f;

#pragma unroll 1
    for (int ee = 0; ee < ecnt; ee++) {
        const int e    = e0 + ee;
        const int base = e * NN + o;

        // ---- issue all global loads up front (MLP) ----
        const float4 w4 = *reinterpret_cast<const float4*>(W + base);
        const float4 f4 = *reinterpret_cast<const float4*>(frac + base);
        const float  sp = __ldg(signs_pre + e);

        float4 dm4[DD];
#pragma unroll
        for (int d = 0; d < DD; d++)
            dm4[d] = *reinterpret_cast<const float4*>(dm + d * (NN * NN) + base);

        float4 wl4[4];
#pragma unroll
        for (int bi = 0; bi < 4; bi++) {
            const int b = ty * 4 + bi;
            wl4[bi] = *reinterpret_cast<const float4*>(Wlong + b * (NN * NN) + base);
        }

        // ---- P/Q from W, frac, sign ----
        const float s = (sp > 0.0f) ? 1.0f : ((sp < 0.0f) ? -1.0f : 0.0f);
        float wv[4] = {w4.x, w4.y, w4.z, w4.w};
        float fv[4] = {f4.x, f4.y, f4.z, f4.w};
        float P[4], Q[4];
#pragma unroll
        for (int oi = 0; oi < 4; oi++) {
            const bool m = wv[oi] > 0.0f;
            P[oi] = m ? s * wv[oi] * (1.0f - fv[oi]) : 0.0f;
            Q[oi] = m ? s * fv[oi] : 0.0f;
        }

        // ---- S[bi][oi] = sum_d A[d][b] * dm[d][o] ----
        float S[4][4];
#pragma unroll
        for (int bi = 0; bi < 4; bi++)
#pragma unroll
            for (int oi = 0; oi < 4; oi++) S[bi][oi] = 0.0f;

#pragma unroll
        for (int d = 0; d < DD; d++) {
            const float4 a4 = *reinterpret_cast<const float4*>(
                A_sm + ee * (DD * BB) + d * BB + ty * 4);
            const float av[4] = {a4.x, a4.y, a4.z, a4.w};
            const float dv[4] = {dm4[d].x, dm4[d].y, dm4[d].z, dm4[d].w};
#pragma unroll
            for (int bi = 0; bi < 4; bi++)
#pragma unroll
                for (int oi = 0; oi < 4; oi++)
                    S[bi][oi] = fmaf(av[bi], dv[oi], S[bi][oi]);
        }

        // ---- acc += (P + Q*Wlong) * S ----
#pragma unroll
        for (int bi = 0; bi < 4; bi++) {
            const float wlv[4] = {wl4[bi].x, wl4[bi].y, wl4[bi].z, wl4[bi].w};
#pragma unroll
            for (int oi = 0; oi < 4; oi++) {
                const float t = fmaf(Q[oi], wlv[oi], P[oi]);
                acc[bi][oi] = fmaf(t, S[bi][oi], acc[bi][oi]);
            }
        }
    }

    // write deterministic partials
#pragma unroll
    for (int bi = 0; bi < 4; bi++) {
        const int b = ty * 4 + bi;
        float4 v = make_float4(acc[bi][0], acc[bi][1], acc[bi][2], acc[bi][3]);
        *reinterpret_cast<float4*>(g_partial + (split * BB + b) * NN + o) = v;
    }
}

__global__ void reduce_partials(float* __restrict__ out) {
    const int i = blockIdx.x * blockDim.x + threadIdx.x;   // i = b*NN + o
    if (i >= BB * NN) return;
    float sum = 0.0f;
#pragma unroll
    for (int sp = 0; sp < ESPLIT; sp++)
        sum += g_partial[sp * (BB * NN) + i];
    out[i] = sum;
}

extern "C" void kernel_launch(void* const* d_in, const int* in_sizes, int n_in,
                              void* d_out, int out_size) {
    const float* W         = (const float*)d_in[0];  // (N,N)
    const float* Wlong     = (const float*)d_in[1];  // (B,N,N)
    const float* Wshort    = (const float*)d_in[2];  // (D,B,N)
    const float* Xd        = (const float*)d_in[3];  // (D,B,N)
    const float* delaymap  = (const float*)d_in[4];  // (D,N,N)
    const float* STDP_frac = (const float*)d_in[5];  // (N,N)
    const float* signs_pre = (const float*)d_in[6];  // (N,)
    float* out = (float*)d_out;                      // (B,N)

    dim3 tgrid(NN / 32, (DD * BB) / 32);   // (64, 4)
    dim3 tblock(32, 8);
    prep_A_t<<<tgrid, tblock>>>(Xd, Wshort);

    dim3 grid(NN / OTILE, ESPLIT);   // (8, 37) = 296 blocks
    dim3 block(64, 4);
    delta_syn_main<<<grid, block>>>(W, Wlong, delaymap, STDP_frac, signs_pre);

    reduce_partials<<<(BB * NN + 255) / 256, 256>>>(out);
}